// round 8
// baseline (speedup 1.0000x reference)
#include <cuda_runtime.h>
#include <cstdint>

#define EMBED     1024
#define STEPS     8
#define NF        16     // 2*STEPS features
#define NPAIR     16     // duplicated feature pairs per token (one per feature)
#define GRID      296    // 2 CTAs per SM on 148-SM GB300
#define NTHREADS  256    // 256 threads * 4 dims = 1024 embed dims
#define DPT       4      // embed dims per thread (2 output f32x2 pairs)
#define MAXTOK    224    // >= ceil(65536/296) = 222

__device__ __forceinline__ unsigned long long pack2(float a, float b) {
    unsigned long long r;
    asm("mov.b64 %0, {%1, %2};" : "=l"(r) : "f"(a), "f"(b));
    return r;
}

__global__ void __launch_bounds__(NTHREADS, 2)
fractal_embed_kernel(const int*   __restrict__ token_ids,
                     const float* __restrict__ c_table,
                     const float* __restrict__ W,
                     const float* __restrict__ scale_p,
                     float*       __restrict__ out,
                     int n_tokens)
{
    // Duplicated-pair feature tile: feats_s[t] = [(f0,f0),(f1,f1),...,(f15,f15)]
    __shared__ __align__(16) float feats_s[MAXTOK][2 * NF];

    const int tid   = threadIdx.x;
    const int bid   = blockIdx.x;
    const float scale = *scale_p;

    // Balanced contiguous token slice for this CTA
    const int start = (int)(((long long)bid)     * n_tokens / GRID);
    const int end   = (int)(((long long)bid + 1) * n_tokens / GRID);
    const int cnt   = end - start;           // 221 or 222 for 65536/296

    // ---- Phase A: Julia features, duplicated pairs into smem ----
    for (int t = tid; t < cnt; t += NTHREADS) {
        const int   tok = token_ids[start + t];
        const float cr  = c_table[2 * tok];
        const float ci  = c_table[2 * tok + 1];
        float zr = 0.f, zi = 0.f;
        float2* row = reinterpret_cast<float2*>(feats_s[t]);
        #pragma unroll
        for (int s = 0; s < STEPS; ++s) {
            const float nzr = zr * zr - zi * zi + cr;
            const float nzi = 2.f * zr * zi + ci;
            zr = nzr; zi = nzi;
            row[2 * s]     = make_float2(zr, zr);
            row[2 * s + 1] = make_float2(zi, zi);
        }
    }

    // ---- W as output-pair-packed registers: w2[j][k] = (W[d0+2j][k], W[d0+2j+1][k]) * scale ----
    const int d0 = tid * DPT;
    unsigned long long w2[2][NPAIR];         // 32 u64 = 64 regs
    #pragma unroll
    for (int j = 0; j < 2; ++j) {
        const float* wr0 = W + (size_t)(d0 + 2 * j)     * NF;
        const float* wr1 = W + (size_t)(d0 + 2 * j + 1) * NF;
        #pragma unroll
        for (int k = 0; k < NPAIR; ++k)
            w2[j][k] = pack2(wr0[k] * scale, wr1[k] * scale);
    }
    __syncthreads();

    // ---- Phase B: one token per iteration; acc pairs ARE the outputs ----
    float* outp = out + (size_t)start * EMBED + d0;

    #pragma unroll 1
    for (int t = 0; t < cnt; ++t) {
        // 16 duplicated feature pairs via 8x LDS.128 (warp-uniform broadcast)
        unsigned long long f2[NPAIR];
        {
            const ulonglong2* fp = reinterpret_cast<const ulonglong2*>(feats_s[t]);
            #pragma unroll
            for (int q = 0; q < 8; ++q) {
                ulonglong2 v = fp[q];
                f2[2 * q]     = v.x;
                f2[2 * q + 1] = v.y;
            }
        }

        // 4 independent chains: (pair j) x (even/odd k), depth 8 each
        unsigned long long a0e = 0ull, a0o = 0ull, a1e = 0ull, a1o = 0ull;
        #pragma unroll
        for (int k = 0; k < NPAIR; k += 2) {
            asm("fma.rn.f32x2 %0, %1, %2, %0;" : "+l"(a0e) : "l"(f2[k]),     "l"(w2[0][k]));
            asm("fma.rn.f32x2 %0, %1, %2, %0;" : "+l"(a1e) : "l"(f2[k]),     "l"(w2[1][k]));
            asm("fma.rn.f32x2 %0, %1, %2, %0;" : "+l"(a0o) : "l"(f2[k + 1]), "l"(w2[0][k + 1]));
            asm("fma.rn.f32x2 %0, %1, %2, %0;" : "+l"(a1o) : "l"(f2[k + 1]), "l"(w2[1][k + 1]));
        }

        unsigned long long o0, o1;
        asm("add.rn.f32x2 %0, %1, %2;" : "=l"(o0) : "l"(a0e), "l"(a0o));
        asm("add.rn.f32x2 %0, %1, %2;" : "=l"(o1) : "l"(a1e), "l"(a1o));

        // 16B streaming store: (out[d0], out[d0+1], out[d0+2], out[d0+3])
        asm volatile("st.global.cs.v2.u64 [%0], {%1, %2};"
                     :: "l"(outp), "l"(o0), "l"(o1) : "memory");
        outp += EMBED;
    }
}

extern "C" void kernel_launch(void* const* d_in, const int* in_sizes, int n_in,
                              void* d_out, int out_size)
{
    const int*   token_ids = (const int*)  d_in[0];
    const float* c_table   = (const float*)d_in[1];
    const float* W         = (const float*)d_in[2];
    const float* scale_p   = (const float*)d_in[3];
    float*       out       = (float*)d_out;

    const int n_tokens = in_sizes[0];
    fractal_embed_kernel<<<GRID, NTHREADS>>>(token_ids, c_table, W, scale_p, out, n_tokens);
}